// round 9
// baseline (speedup 1.0000x reference)
#include <cuda_runtime.h>
#include <math.h>
#include <stdint.h>

// Problem constants
#define NB 2
#define SSEQ 4096
#define NV 50257
#define NH 1024
#define MASKID 50256
#define TPB 256
#define WPB 8                     // warps per block
#define NROWS (NB * SSEQ)         // 8192
#define NBLK (NROWS / WPB)        // 1024
#define CPL 8                     // float4 chunks per lane (1024/4/32)
#define ROWB 4096                 // bytes per row

__device__ __forceinline__ uint32_t smem_u32(const void* p) {
    uint32_t a;
    asm("{ .reg .u64 t; cvta.to.shared.u64 t, %1; cvt.u32.u64 %0, t; }"
        : "=r"(a) : "l"(p));
    return a;
}
#define BULK_S2G(dst, src, sz) \
    asm volatile("cp.async.bulk.global.shared::cta.bulk_group [%0], [%1], %2;" \
                 :: "l"(dst), "r"(src), "r"(sz) : "memory")
#define BULK_COMMIT() asm volatile("cp.async.bulk.commit_group;" ::: "memory")
#define BULK_WAITG0() asm volatile("cp.async.bulk.wait_group 0;" ::: "memory")
#define FENCE_ASYNC() asm volatile("fence.proxy.async.shared::cta;" ::: "memory")

__device__ __forceinline__ void ins3(float v, int i,
                                     float& v0, int& i0,
                                     float& v1, int& i1,
                                     float& v2, int& i2)
{
    if (v > v0 || (v == v0 && i < i0)) {
        v2 = v1; i2 = i1; v1 = v0; i1 = i0; v0 = v; i0 = i;
    } else if (v > v1 || (v == v1 && i < i1)) {
        v2 = v1; i2 = i1; v1 = v; i1 = i;
    } else if (v > v2 || (v == v2 && i < i2)) {
        v2 = v; i2 = i;
    }
}

__global__ __launch_bounds__(TPB)
void softmask_kernel(const void* __restrict__ x_t_raw,
                     const float* __restrict__ probs,
                     const float* __restrict__ embed,
                     const float* __restrict__ p_os,
                     const float* __restrict__ p_oa,
                     const float* __restrict__ p_ob,
                     float* __restrict__ out)
{
    __shared__ __align__(128) float4 stage[WPB][ROWB / 16];   // 32 KB: 4 KB per warp

    const int warp = threadIdx.x >> 5;
    const int lane = threadIdx.x & 31;
    const int row  = blockIdx.x * WPB + warp;

    // ---- dtype-width detection (int64 vs int32) ----
    const int* xi = (const int*)x_t_raw;
    const bool is64 = (xi[1] == 0) & (xi[3] == 0) & (xi[5] == 0) & (xi[7] == 0);
    const int tok = is64 ? (int)((const long long*)x_t_raw)[row] : xi[row];

    if (tok != MASKID) {
        // ---- fast path: 8 front-batched LDG.128 -> SMEM stage -> one 4KB bulk store ----
        const float4* erow = (const float4*)(embed + (size_t)tok * NH);
        float4 v[CPL];
#pragma unroll
        for (int j = 0; j < CPL; ++j) v[j] = erow[lane + 32 * j];
#pragma unroll
        for (int j = 0; j < CPL; ++j) stage[warp][lane + 32 * j] = v[j];

        __syncwarp();
        if (lane == 0) {
            FENCE_ASYNC();   // make STS visible to the async (TMA) proxy
            BULK_S2G((uint64_t)(char*)(out + (size_t)row * NH),
                     smem_u32(&stage[warp][0]), ROWB);
            BULK_COMMIT();
            BULK_WAITG0();   // keep smem stage live until the store drains
        }
        return;
    }

    // ---- rare heavy path: warp-local top-3 + entropy over the vocab row ----
    const float* p = probs + (size_t)row * NV;

    float v0 = -1e30f, v1 = -1e30f, v2 = -1e30f;
    int   i0 = 0x7fffffff, i1 = 0x7fffffff, i2 = 0x7fffffff;
    float ent = 0.0f;

    for (int i = lane; i < NV; i += 32) {
        float v = __ldcs(&p[i]);
        if (v > 0.0f) ent -= v * __logf(v);
        ins3(v, i, v0, i0, v1, i1, v2, i2);
    }
#pragma unroll
    for (int off = 16; off > 0; off >>= 1) {
        ent += __shfl_xor_sync(0xffffffffu, ent, off);
        float ov0 = __shfl_xor_sync(0xffffffffu, v0, off);
        float ov1 = __shfl_xor_sync(0xffffffffu, v1, off);
        float ov2 = __shfl_xor_sync(0xffffffffu, v2, off);
        int   oi0 = __shfl_xor_sync(0xffffffffu, i0, off);
        int   oi1 = __shfl_xor_sync(0xffffffffu, i1, off);
        int   oi2 = __shfl_xor_sync(0xffffffffu, i2, off);
        ins3(ov0, oi0, v0, i0, v1, i1, v2, i2);
        ins3(ov1, oi1, v0, i0, v1, i1, v2, i2);
        ins3(ov2, oi2, v0, i0, v1, i1, v2, i2);
    }

    float ssum = v0 + v1 + v2 + 1e-10f;
    float w0 = v0 / ssum, w1 = v1 / ssum, w2 = v2 / ssum;

    float os = p_os[0], oa = p_oa[0], ob = p_ob[0];
    float sp_oa = (oa > 20.0f) ? oa : log1pf(expf(oa));
    float sp_ob = (ob > 20.0f) ? ob : log1pf(expf(ob));
    float sig_os = 1.0f / (1.0f + expf(-os));
    float arg = sp_oa * (sp_ob - ent);
    float lam = sig_os * (1.0f / (1.0f + expf(-arg)));

    const float4* e0 = (const float4*)(embed + (size_t)i0 * NH);
    const float4* e1 = (const float4*)(embed + (size_t)i1 * NH);
    const float4* e2 = (const float4*)(embed + (size_t)i2 * NH);
    const float4* er = (const float4*)(embed + (size_t)MASKID * NH);
    float4* orow = (float4*)(out + (size_t)row * NH);

#pragma unroll
    for (int j = 0; j < CPL; ++j) {
        int c = lane + 32 * j;
        float4 a = e0[c], b = e1[c], cc = e2[c], r = er[c];
        float4 o;
        o.x = (1.0f - lam) * r.x + lam * (w0 * a.x + w1 * b.x + w2 * cc.x);
        o.y = (1.0f - lam) * r.y + lam * (w0 * a.y + w1 * b.y + w2 * cc.y);
        o.z = (1.0f - lam) * r.z + lam * (w0 * a.z + w1 * b.z + w2 * cc.z);
        o.w = (1.0f - lam) * r.w + lam * (w0 * a.w + w1 * b.w + w2 * cc.w);
        __stcs(&orow[c], o);
    }
}

extern "C" void kernel_launch(void* const* d_in, const int* in_sizes, int n_in,
                              void* d_out, int out_size)
{
    (void)in_sizes; (void)n_in; (void)out_size;
    const void*  x_t   = d_in[0];
    const float* probs = (const float*)d_in[1];
    const float* embed = (const float*)d_in[2];
    const float* om_s  = (const float*)d_in[3];
    const float* om_a  = (const float*)d_in[4];
    const float* om_b  = (const float*)d_in[5];
    float* out = (float*)d_out;

    softmask_kernel<<<NBLK, TPB>>>(x_t, probs, embed, om_s, om_a, om_b, out);
}

// round 10
// speedup vs baseline: 1.5714x; 1.5714x over previous
#include <cuda_runtime.h>
#include <math.h>
#include <stdint.h>

// Problem constants
#define NB 2
#define SSEQ 4096
#define NV 50257
#define NH 1024
#define MASKID 50256
#define TPB 256
#define WPB 8
#define NCTA 148                     // one CTA per SM, exactly one wave
#define NWARPS (NCTA * WPB)          // 1184
#define NROWS (NB * SSEQ)            // 8192
#define CPL 8                        // float4 chunks per lane

__device__ __forceinline__ void ins3(float v, int i,
                                     float& v0, int& i0,
                                     float& v1, int& i1,
                                     float& v2, int& i2)
{
    if (v > v0 || (v == v0 && i < i0)) {
        v2 = v1; i2 = i1; v1 = v0; i1 = i0; v0 = v; i0 = i;
    } else if (v > v1 || (v == v1 && i < i1)) {
        v2 = v1; i2 = i1; v1 = v; i1 = i;
    } else if (v > v2 || (v == v2 && i < i2)) {
        v2 = v; i2 = i;
    }
}

// Rare path: one warp computes the full masked-row output.
__device__ void heavy_row(int row, int lane,
                          const float* __restrict__ probs,
                          const float* __restrict__ embed,
                          const float* __restrict__ p_os,
                          const float* __restrict__ p_oa,
                          const float* __restrict__ p_ob,
                          float* __restrict__ out)
{
    const float* p = probs + (size_t)row * NV;

    float v0 = -1e30f, v1 = -1e30f, v2 = -1e30f;
    int   i0 = 0x7fffffff, i1 = 0x7fffffff, i2 = 0x7fffffff;
    float ent = 0.0f;

    for (int i = lane; i < NV; i += 32) {
        float v = __ldcs(&p[i]);
        if (v > 0.0f) ent -= v * __logf(v);
        ins3(v, i, v0, i0, v1, i1, v2, i2);
    }
#pragma unroll
    for (int off = 16; off > 0; off >>= 1) {
        ent += __shfl_xor_sync(0xffffffffu, ent, off);
        float ov0 = __shfl_xor_sync(0xffffffffu, v0, off);
        float ov1 = __shfl_xor_sync(0xffffffffu, v1, off);
        float ov2 = __shfl_xor_sync(0xffffffffu, v2, off);
        int   oi0 = __shfl_xor_sync(0xffffffffu, i0, off);
        int   oi1 = __shfl_xor_sync(0xffffffffu, i1, off);
        int   oi2 = __shfl_xor_sync(0xffffffffu, i2, off);
        ins3(ov0, oi0, v0, i0, v1, i1, v2, i2);
        ins3(ov1, oi1, v0, i0, v1, i1, v2, i2);
        ins3(ov2, oi2, v0, i0, v1, i1, v2, i2);
    }

    float ssum = v0 + v1 + v2 + 1e-10f;
    float w0 = v0 / ssum, w1 = v1 / ssum, w2 = v2 / ssum;

    float os = p_os[0], oa = p_oa[0], ob = p_ob[0];
    float sp_oa = (oa > 20.0f) ? oa : log1pf(expf(oa));
    float sp_ob = (ob > 20.0f) ? ob : log1pf(expf(ob));
    float sig_os = 1.0f / (1.0f + expf(-os));
    float arg = sp_oa * (sp_ob - ent);
    float lam = sig_os * (1.0f / (1.0f + expf(-arg)));

    const float4* e0 = (const float4*)(embed + (size_t)i0 * NH);
    const float4* e1 = (const float4*)(embed + (size_t)i1 * NH);
    const float4* e2 = (const float4*)(embed + (size_t)i2 * NH);
    const float4* er = (const float4*)(embed + (size_t)MASKID * NH);
    float4* orow = (float4*)(out + (size_t)row * NH);

#pragma unroll
    for (int j = 0; j < CPL; ++j) {
        int c = lane + 32 * j;
        float4 a = e0[c], b = e1[c], cc = e2[c], r = er[c];
        float4 o;
        o.x = (1.0f - lam) * r.x + lam * (w0 * a.x + w1 * b.x + w2 * cc.x);
        o.y = (1.0f - lam) * r.y + lam * (w0 * a.y + w1 * b.y + w2 * cc.y);
        o.z = (1.0f - lam) * r.z + lam * (w0 * a.z + w1 * b.z + w2 * cc.z);
        o.w = (1.0f - lam) * r.w + lam * (w0 * a.w + w1 * b.w + w2 * cc.w);
        orow[c] = o;
    }
}

#define LDROW(buf, tk)                                                     \
    do {                                                                   \
        const float4* _e = (const float4*)(embed + (size_t)(tk) * NH);     \
        _Pragma("unroll")                                                  \
        for (int _j = 0; _j < CPL; ++_j) (buf)[_j] = _e[lane + 32 * _j];   \
    } while (0)

#define STROW(r, buf)                                                      \
    do {                                                                   \
        float4* _o = (float4*)(out + (size_t)(r) * NH);                    \
        _Pragma("unroll")                                                  \
        for (int _j = 0; _j < CPL; ++_j) __stcs(&_o[lane + 32 * _j], (buf)[_j]); \
    } while (0)

__global__ __launch_bounds__(TPB)
void softmask_kernel(const void* __restrict__ x_t_raw,
                     const float* __restrict__ probs,
                     const float* __restrict__ embed,
                     const float* __restrict__ p_os,
                     const float* __restrict__ p_oa,
                     const float* __restrict__ p_ob,
                     float* __restrict__ out)
{
    const int warp  = threadIdx.x >> 5;
    const int lane  = threadIdx.x & 31;
    const int gwarp = blockIdx.x * WPB + warp;

    // dtype-width detection (int64 vs int32)
    const int* xi = (const int*)x_t_raw;
    const bool is64 = (xi[1] == 0) & (xi[3] == 0) & (xi[5] == 0) & (xi[7] == 0);
    const long long* xl = (const long long*)x_t_raw;

    // row count for this warp (rows gwarp, gwarp+NWARPS, ...)
    int nrows = 0;
    bool anymask = false;
    for (int r = gwarp; r < NROWS; r += NWARPS) {
        int tk = is64 ? (int)xl[r] : xi[r];
        anymask |= (tk == MASKID);
        ++nrows;
    }

    float4 buf0[CPL], buf1[CPL];

    if (!anymask) {
        // ---- software-pipelined copy: load row i+1 before storing row i ----
        int rowP = gwarp;
        int tk = is64 ? (int)xl[rowP] : xi[rowP];
        LDROW(buf0, tk);

        int i = 1;
        for (; i + 1 < nrows; i += 2) {
            const int rA = gwarp + i * NWARPS;
            const int rB = rA + NWARPS;
            int tA = is64 ? (int)xl[rA] : xi[rA];
            LDROW(buf1, tA);
            STROW(rowP, buf0);            // waits on buf0; buf1 loads in flight
            int tB = is64 ? (int)xl[rB] : xi[rB];
            LDROW(buf0, tB);
            STROW(rA, buf1);
            rowP = rB;
        }
        if (i < nrows) {                  // one leftover row
            const int rA = gwarp + i * NWARPS;
            int tA = is64 ? (int)xl[rA] : xi[rA];
            LDROW(buf1, tA);
            STROW(rowP, buf0);
            STROW(rA, buf1);
        } else {
            STROW(rowP, buf0);
        }
        return;
    }

    // ---- fallback (warp has a mask row — vanishingly rare): simple per-row ----
    for (int r = gwarp; r < NROWS; r += NWARPS) {
        int tk = is64 ? (int)xl[r] : xi[r];
        if (tk != MASKID) {
            LDROW(buf0, tk);
            STROW(r, buf0);
        } else {
            heavy_row(r, lane, probs, embed, p_os, p_oa, p_ob, out);
        }
    }
}

extern "C" void kernel_launch(void* const* d_in, const int* in_sizes, int n_in,
                              void* d_out, int out_size)
{
    (void)in_sizes; (void)n_in; (void)out_size;
    const void*  x_t   = d_in[0];
    const float* probs = (const float*)d_in[1];
    const float* embed = (const float*)d_in[2];
    const float* om_s  = (const float*)d_in[3];
    const float* om_a  = (const float*)d_in[4];
    const float* om_b  = (const float*)d_in[5];
    float* out = (float*)d_out;

    softmask_kernel<<<NCTA, TPB>>>(x_t, probs, embed, om_s, om_a, om_b, out);
}